// round 6
// baseline (speedup 1.0000x reference)
#include <cuda_runtime.h>

// Fused ModernNet inference — warp-pair cooperative version.
// Pairs (warp 2p, 2p+1) share samples {2p, 2p+1}; pair-local named barriers
// (bar.sync id,64) keep 4 independent pairs per block (no block-wide sync
// after phase 1). Phase 3 streams each input row once (col-split across the
// pair); fc1 weight loads amortized across the pair.

#define SPB 8
#define NT  256

// ---- padded weight globals (filled by prep kernel each launch) ----
__device__ float gW1p[12 * 28];     // conv1 w: [ch][28] (25 + 3 zero pad)
__device__ float gW2p[12 * 228];    // conv2 w: [oc][ic*28 + k] (+4 tail pad)
__device__ float gW3t[30 * 192];    // fc1 w transposed: [n][192]

__global__ void prep_kernel(const float* __restrict__ H1w,
                            const float* __restrict__ H2w,
                            const float* __restrict__ H3w) {
    const int i = blockIdx.x * 256 + threadIdx.x;
    if (i < 336) {
        int ch = i / 28, r = i % 28;
        gW1p[i] = (r < 25) ? H1w[ch * 25 + r] : 0.f;
    }
    if (i < 2736) {
        int oc = i / 228, rem = i % 228;
        int ic = rem / 28, r = rem % 28;
        gW2p[i] = (ic < 8 && r < 25) ? H2w[oc * 200 + ic * 25 + r] : 0.f;
    }
    if (i < 5760) {
        int n = i / 192, k = i % 192;
        gW3t[i] = H3w[k * 30 + n];
    }
}

// c1 channel offset with bank-decollision swizzle (+8 floats for ch 4..7)
#define C1OFF(ch) ((ch) * 148 + ((((ch) >> 2) & 1) << 3))
#define C1_SAMPLE_STRIDE 1796   // == 4 mod 32 -> sample pairs on distinct banks
#define W2_OC_STRIDE 228
#define C2_STRIDE 196           // == 4 mod 32
#define F1_STRIDE 36

// ---- shared memory float offsets (all multiples of 4) ----
#define OFF_W1   0       // 336
#define OFF_B1   336     // 768
#define OFF_W2   1104    // 2736
#define OFF_B2   3840    // 192
#define OFF_WOT  4032    // 360 (fc2 w transposed, rows padded to 36)
#define OFF_BO   4392    // 12
#define OFF_B3   4404    // 32
#define OFF_XIN  4436    // 8 * 400
#define OFF_C1   7636    // 8 * 1796 = 14368
#define OFF_C2   22004   // 8 * 196 = 1568
#define OFF_F1   23572   // 8 * 36 = 288
#define SMEM_FLOATS 23860   // 95440 bytes -> 2 blocks/SM

#define PAIR_BAR(id) asm volatile("bar.sync %0, %1;" :: "r"(id), "r"(64) : "memory")

__global__ void __launch_bounds__(NT, 2) modernnet_kernel(
    const float* __restrict__ x,
    const float* __restrict__ H1b, const float* __restrict__ H2b,
    const float* __restrict__ H3b,
    const float* __restrict__ outw, const float* __restrict__ outb,
    float* __restrict__ out, int B)
{
    extern __shared__ float sm[];
    const int tid  = threadIdx.x;
    const int warp = tid >> 5;
    const int lane = tid & 31;
    const int blockSample = blockIdx.x * SPB;
    const int pairBase = warp & ~1;          // first warp (== first sample) of pair
    const int barid = (warp >> 1) + 1;       // named barrier id 1..4

    float* sW1  = sm + OFF_W1;
    float* sB1  = sm + OFF_B1;
    float* sW2  = sm + OFF_W2;
    float* sB2  = sm + OFF_B2;
    float* sWoT = sm + OFF_WOT;
    float* sBo  = sm + OFF_BO;
    float* sB3  = sm + OFF_B3;
    float* sXin = sm + OFF_XIN;
    float* sC1  = sm + OFF_C1;
    float* sC2  = sm + OFF_C2;
    float* sF1  = sm + OFF_F1;

    // ---------- Phase 0: weight copies + pad fills ----------
    {
        float4* d = (float4*)sW1;
        const float4* s = (const float4*)gW1p;
        for (int i = tid; i < 84; i += NT) d[i] = s[i];
    }
    {
        float4* d = (float4*)sB1;
        const float4* s = (const float4*)H1b;
        for (int i = tid; i < 192; i += NT) d[i] = s[i];
    }
    {
        float4* d = (float4*)sW2;
        const float4* s = (const float4*)gW2p;
        for (int i = tid; i < 684; i += NT) d[i] = s[i];
    }
    {
        float4* d = (float4*)sB2;
        const float4* s = (const float4*)H2b;
        for (int i = tid; i < 48; i += NT) d[i] = s[i];
    }
    for (int i = tid; i < 360; i += NT) {              // fc2 w transposed
        int m = i / 36, k = i % 36;
        sWoT[i] = (k < 30) ? outw[k * 10 + m] : 0.f;
    }
    if (tid < 12) sBo[tid] = (tid < 10) ? outb[tid] : 0.f;
    if (tid < 32) sB3[tid] = (tid < 30) ? H3b[tid] : 0.f;
    for (int i = tid; i < 288; i += NT) sF1[i] = 0.f;  // fc2 reads padded tail
    {
        const float4 m1 = make_float4(-1.f, -1.f, -1.f, -1.f);
        float4* f = (float4*)sXin;
        for (int i = tid; i < (SPB * 400) / 4; i += NT) f[i] = m1;
        float4* g = (float4*)sC1;
        for (int i = tid; i < (SPB * C1_SAMPLE_STRIDE) / 4; i += NT) g[i] = m1;
    }
    // Fill -> scatter ordering across whole block (required!)
    __syncthreads();

    // ---------- Phase 1: inputs into padded 20x20 buffers ----------
    if (blockSample + SPB <= B) {
        const float4* gx = (const float4*)(x + (size_t)blockSample * 256);
        for (int i = tid; i < SPB * 64; i += NT) {
            float4 v = gx[i];
            int s = i >> 6, rem = i & 63;
            int ih = rem >> 2, iw = (rem & 3) * 4;
            float* d = sXin + s * 400 + (ih + 2) * 20 + iw + 2;
            ((float2*)d)[0] = make_float2(v.x, v.y);
            ((float2*)d)[1] = make_float2(v.z, v.w);
        }
    } else {
        const int nval = (B - blockSample) * 256;
        const float* gx = x + (size_t)blockSample * 256;
        for (int i = tid; i < nval; i += NT) {
            int s = i >> 8, p = i & 255;
            int ih = p >> 4, iw = p & 15;
            sXin[s * 400 + (ih + 2) * 20 + (iw + 2)] = gx[i];
        }
    }
    __syncthreads();

    // ---------- Phase 2: conv1 5x5 s2 (warp = its own sample) ----------
    {
        const int q   = lane & 15;
        const int chg = lane >> 4;
        const int oh0 = (q >> 2) << 1;
        const int ow0 = (q & 3) << 1;
        const float* pbase = sXin + warp * 400 + (2 * oh0) * 20 + 2 * ow0;

        float p[7][8];
        #pragma unroll
        for (int i = 0; i < 7; i++) {
            float4 v0 = *(const float4*)(pbase + i * 20);
            float4 v1 = *(const float4*)(pbase + i * 20 + 4);
            p[i][0] = v0.x; p[i][1] = v0.y; p[i][2] = v0.z; p[i][3] = v0.w;
            p[i][4] = v1.x; p[i][5] = v1.y; p[i][6] = v1.z; p[i][7] = v1.w;
        }

        float* c1 = sC1 + warp * C1_SAMPLE_STRIDE;
        #pragma unroll
        for (int cc = 0; cc < 6; cc++) {
            const int c = chg * 6 + cc;
            const float4* w4 = (const float4*)(sW1 + c * 28);
            float w[28];
            #pragma unroll
            for (int i = 0; i < 7; i++) {
                float4 v = w4[i];
                w[4 * i] = v.x; w[4 * i + 1] = v.y;
                w[4 * i + 2] = v.z; w[4 * i + 3] = v.w;
            }
            float a00 = 0.f, a01 = 0.f, a10 = 0.f, a11 = 0.f;
            #pragma unroll
            for (int ki = 0; ki < 5; ki++)
                #pragma unroll
                for (int kj = 0; kj < 5; kj++) {
                    const float wv = w[ki * 5 + kj];
                    a00 = fmaf(p[ki][kj],         wv, a00);
                    a01 = fmaf(p[ki][kj + 2],     wv, a01);
                    a10 = fmaf(p[ki + 2][kj],     wv, a10);
                    a11 = fmaf(p[ki + 2][kj + 2], wv, a11);
                }
            const float* b = sB1 + c * 64;
            float2 b0 = *(const float2*)(b + oh0 * 8 + ow0);
            float2 b1 = *(const float2*)(b + (oh0 + 1) * 8 + ow0);
            float* o = c1 + C1OFF(c);
            *(float2*)(o + (oh0 + 2) * 12 + ow0 + 2) =
                make_float2(fmaxf(a00 + b0.x, 0.f), fmaxf(a01 + b0.y, 0.f));
            *(float2*)(o + (oh0 + 3) * 12 + ow0 + 2) =
                make_float2(fmaxf(a10 + b1.x, 0.f), fmaxf(a11 + b1.y, 0.f));
        }
    }
    PAIR_BAR(barid);   // partner's sC1 needed below

    // ---------- Phase 3: grouped conv2, pair-cooperative ----------
    // lane = (oc = lane>>1, sidx = lane&1); warp parity picks output cols:
    // warp even -> out cols {0,1}, warp odd -> {2,3}. Each lane computes a
    // full 4-row strip; each input row is loaded exactly once per (ic).
    if (lane < 24) {
        const int oc   = lane >> 1;
        const int sidx = lane & 1;
        const int colh = warp & 1;
        const int g    = oc >> 2;
        const float* c1    = sC1 + (pairBase + sidx) * C1_SAMPLE_STRIDE;
        const float* wbase = sW2 + oc * W2_OC_STRIDE;

        float acc[4][2];
        #pragma unroll
        for (int r = 0; r < 4; r++) { acc[r][0] = 0.f; acc[r][1] = 0.f; }

        #pragma unroll
        for (int ic = 0; ic < 8; ic++) {
            const int inch = ic + ((g == 1) ? 4 : ((g == 2 && ic >= 4) ? 4 : 0));
            const float* ib = c1 + C1OFF(inch) + colh * 4;

            const float4* w4 = (const float4*)(wbase + ic * 28);
            float w[28];
            #pragma unroll
            for (int i = 0; i < 7; i++) {
                float4 v = w4[i];
                w[4 * i] = v.x; w[4 * i + 1] = v.y;
                w[4 * i + 2] = v.z; w[4 * i + 3] = v.w;
            }

            // stream input rows 0..10 once; row8 = input cols [4*colh .. +7]
            #pragma unroll
            for (int R = 0; R < 11; R++) {
                float4 f0 = *(const float4*)(ib + R * 12);
                float4 f1 = *(const float4*)(ib + R * 12 + 4);
                float row8[8] = {f0.x, f0.y, f0.z, f0.w, f1.x, f1.y, f1.z, f1.w};
                #pragma unroll
                for (int r = 0; r < 4; r++) {
                    const int ki = R - 2 * r;
                    if (ki >= 0 && ki <= 4) {
                        #pragma unroll
                        for (int kj = 0; kj < 5; kj++) {
                            const float wv = w[ki * 5 + kj];
                            acc[r][0] = fmaf(row8[kj],     wv, acc[r][0]);
                            acc[r][1] = fmaf(row8[kj + 2], wv, acc[r][1]);
                        }
                    }
                }
            }
        }

        // epilogue: bias + relu; out col = 2*colh + c
        float* c2 = sC2 + (pairBase + sidx) * C2_STRIDE;
        const int base = oc * 16 + colh * 2;
        #pragma unroll
        for (int r = 0; r < 4; r++) {
            const int idx = base + r * 4;
            float2 b2 = *(const float2*)(sB2 + idx);
            *(float2*)(c2 + idx) =
                make_float2(fmaxf(acc[r][0] + b2.x, 0.f),
                            fmaxf(acc[r][1] + b2.y, 0.f));
        }
    }
    PAIR_BAR(barid);   // both warps wrote both samples' sC2

    // ---------- Phase 4: fc1 192->30, pair-cooperative ----------
    // warp parity picks neuron half; lane = (n2 = lane>>1, sidx = lane&1).
    // Weight rows loaded once per pair (15 rows/warp, shared by 2 sample lanes).
    if (lane < 30) {
        const int n    = (warp & 1) * 15 + (lane >> 1);
        const int sidx = lane & 1;
        const float4* a4 = (const float4*)(sC2 + (pairBase + sidx) * C2_STRIDE);
        const float4* w4 = (const float4*)(gW3t + n * 192);
        float acc0 = 0.f, acc1 = 0.f, acc2 = 0.f, acc3 = 0.f;
        #pragma unroll
        for (int i = 0; i < 48; i++) {
            float4 a = a4[i];
            float4 w = __ldg(w4 + i);
            acc0 = fmaf(a.x, w.x, acc0);
            acc1 = fmaf(a.y, w.y, acc1);
            acc2 = fmaf(a.z, w.z, acc2);
            acc3 = fmaf(a.w, w.w, acc3);
        }
        float acc = (acc0 + acc1) + (acc2 + acc3) + sB3[n];
        sF1[(pairBase + sidx) * F1_STRIDE + n] = fmaxf(acc, 0.f);
    }
    PAIR_BAR(barid);   // sF1 halves from both warps

    // ---------- Phase 5: fc2 30->10 (warp = its own sample) ----------
    if (lane < 10) {
        const float4* f4 = (const float4*)(sF1 + warp * F1_STRIDE);
        const float4* w4 = (const float4*)(sWoT + lane * F1_STRIDE);
        float acc0 = 0.f, acc1 = 0.f, acc2 = 0.f, acc3 = 0.f;
        #pragma unroll
        for (int i = 0; i < 8; i++) {
            float4 a = f4[i];
            float4 w = w4[i];
            acc0 = fmaf(a.x, w.x, acc0);
            acc1 = fmaf(a.y, w.y, acc1);
            acc2 = fmaf(a.z, w.z, acc2);
            acc3 = fmaf(a.w, w.w, acc3);
        }
        const int smp = blockSample + warp;
        if (smp < B)
            out[(size_t)smp * 10 + lane] = (acc0 + acc1) + (acc2 + acc3) + sBo[lane];
    }
}

extern "C" void kernel_launch(void* const* d_in, const int* in_sizes, int n_in,
                              void* d_out, int out_size) {
    const float* x    = (const float*)d_in[0];
    const float* H1w  = (const float*)d_in[1];
    const float* H1b  = (const float*)d_in[2];
    const float* H2w  = (const float*)d_in[3];
    const float* H2b  = (const float*)d_in[4];
    const float* H3w  = (const float*)d_in[5];
    const float* H3b  = (const float*)d_in[6];
    const float* outw = (const float*)d_in[7];
    const float* outb = (const float*)d_in[8];

    const int B = in_sizes[0] / 256;
    const int blocks = (B + SPB - 1) / SPB;
    const size_t smem = SMEM_FLOATS * sizeof(float);

    prep_kernel<<<24, 256>>>(H1w, H2w, H3w);

    cudaFuncSetAttribute(modernnet_kernel,
                         cudaFuncAttributeMaxDynamicSharedMemorySize, (int)smem);

    modernnet_kernel<<<blocks, NT, smem>>>(x, H1b, H2b, H3b, outw, outb,
                                           (float*)d_out, B);
}

// round 8
// speedup vs baseline: 1.5548x; 1.5548x over previous
#include <cuda_runtime.h>

// Fused ModernNet inference — R4 structure + analytic pad folding for conv2.
// The -1 pad ring of conv2's input is folded into a precomputed per-(oc,px)
// bias adjustment; sC1 stores only the 8x8 interior (no pad fill, fewer
// loads, fewer FMAs). Conv1 path, FC path identical to the R4 champion.
// (Resubmission of R7 — prior round died on container infra, no signal.)

#define SPB 8
#define NT  256

// ---- padded weight globals (filled by prep kernel each launch) ----
__device__ float gW1p[12 * 28];     // conv1 w: [ch][28] (25 + 3 zero pad)
__device__ float gW2p[12 * 228];    // conv2 w: [oc][ic*28 + k] (+4 tail pad)
__device__ float gW3p[192 * 32];    // fc1 w:  [k][32] (30 + 2 zero pad)
__device__ float gB2adj[192];       // conv2 bias with -1-border fold

__global__ void prep_kernel(const float* __restrict__ H1w,
                            const float* __restrict__ H2w,
                            const float* __restrict__ H3w,
                            const float* __restrict__ H2b) {
    const int i = blockIdx.x * 256 + threadIdx.x;
    if (i < 336) {
        int ch = i / 28, r = i % 28;
        gW1p[i] = (r < 25) ? H1w[ch * 25 + r] : 0.f;
    }
    if (i < 2736) {
        int oc = i / 228, rem = i % 228;
        int ic = rem / 28, r = rem % 28;
        gW2p[i] = (ic < 8 && r < 25) ? H2w[oc * 200 + ic * 25 + r] : 0.f;
    }
    if (i < 6144) {
        int k = i / 32, n = i % 32;
        gW3p[i] = (n < 30) ? H3w[k * 30 + n] : 0.f;
    }
    if (i < 192) {
        // adjusted conv2 bias: subtract sum of weights over taps that land in
        // the -1 pad ring (padded coords outside [2,9] in either dim)
        int oc = i >> 4, px = i & 15, r = px >> 2, c = px & 3;
        float s = 0.f;
        for (int ki = 0; ki < 5; ki++)
            for (int kj = 0; kj < 5; kj++) {
                int pr = 2 * r + ki, pc = 2 * c + kj;
                if (pr < 2 || pr > 9 || pc < 2 || pc > 9) {
                    for (int ic = 0; ic < 8; ic++)
                        s += H2w[oc * 200 + ic * 25 + ki * 5 + kj];
                }
            }
        gB2adj[i] = H2b[i] - s;
    }
}

// compact interior c1: 8x8 per channel, row stride 12, channel stride 100
// with +4 swizzle for ch 4..7 -> per-instr bank sets {0,20,16,4}/{0,12,16,28}
#define C1COFF(ch) ((ch) * 100 + ((((ch) >> 2) & 1) << 2))
#define C1_SAMPLE 1204
#define W2_OC_STRIDE 228

// ---- shared memory float offsets (all multiples of 4) ----
#define OFF_W1   0       // 336
#define OFF_B1   336     // 768
#define OFF_W2   1104    // 2736
#define OFF_B2   3840    // 192 (adjusted)
#define OFF_WO   4032    // 300
#define OFF_BO   4332    // 12
#define OFF_B3   4344    // 32
#define OFF_XIN  4376    // 8 * 400
#define OFF_C1   7576    // 8 * 1204 = 9632
#define OFF_C2   17208   // 8 * 196 = 1568
#define OFF_F1   18776   // 8 * 32 = 256
#define SMEM_FLOATS 19032   // 76128 bytes

#define C2_STRIDE 196

__global__ void __launch_bounds__(NT, 2) modernnet_kernel(
    const float* __restrict__ x,
    const float* __restrict__ H1b, const float* __restrict__ H3b,
    const float* __restrict__ outw, const float* __restrict__ outb,
    float* __restrict__ out, int B)
{
    extern __shared__ float sm[];
    const int tid  = threadIdx.x;
    const int warp = tid >> 5;
    const int lane = tid & 31;
    const int blockSample = blockIdx.x * SPB;

    float* sW1  = sm + OFF_W1;
    float* sB1  = sm + OFF_B1;
    float* sW2  = sm + OFF_W2;
    float* sB2  = sm + OFF_B2;
    float* sWo  = sm + OFF_WO;
    float* sBo  = sm + OFF_BO;
    float* sB3  = sm + OFF_B3;
    float* sXin = sm + OFF_XIN;
    float* sC1  = sm + OFF_C1;
    float* sC2  = sm + OFF_C2;
    float* sF1  = sm + OFF_F1;

    // ---------- Phase 0: weight copies + input pad fill ----------
    {
        float4* d = (float4*)sW1;
        const float4* s = (const float4*)gW1p;
        for (int i = tid; i < 84; i += NT) d[i] = s[i];
    }
    {
        float4* d = (float4*)sB1;
        const float4* s = (const float4*)H1b;
        for (int i = tid; i < 192; i += NT) d[i] = s[i];
    }
    {
        float4* d = (float4*)sW2;
        const float4* s = (const float4*)gW2p;
        for (int i = tid; i < 684; i += NT) d[i] = s[i];
    }
    {
        float4* d = (float4*)sB2;
        const float4* s = (const float4*)gB2adj;
        for (int i = tid; i < 48; i += NT) d[i] = s[i];
    }
    {
        float4* d = (float4*)sWo;
        const float4* s = (const float4*)outw;
        for (int i = tid; i < 75; i += NT) d[i] = s[i];
    }
    if (tid < 12) sBo[tid] = (tid < 10) ? outb[tid] : 0.f;
    if (tid < 32) sB3[tid] = (tid < 30) ? H3b[tid] : 0.f;
    {
        const float4 m1 = make_float4(-1.f, -1.f, -1.f, -1.f);
        float4* f = (float4*)sXin;
        for (int i = tid; i < (SPB * 400) / 4; i += NT) f[i] = m1;
        // NOTE: no sC1 fill — conv2 pad is folded into gB2adj.
    }
    // Fill -> scatter ordering across whole block (required!)
    __syncthreads();

    // ---------- Phase 1: inputs into padded 20x20 buffers ----------
    if (blockSample + SPB <= B) {
        const float4* gx = (const float4*)(x + (size_t)blockSample * 256);
        for (int i = tid; i < SPB * 64; i += NT) {
            float4 v = gx[i];
            int s = i >> 6, rem = i & 63;
            int ih = rem >> 2, iw = (rem & 3) * 4;
            float* d = sXin + s * 400 + (ih + 2) * 20 + iw + 2;
            ((float2*)d)[0] = make_float2(v.x, v.y);
            ((float2*)d)[1] = make_float2(v.z, v.w);
        }
    } else {
        const int nval = (B - blockSample) * 256;
        const float* gx = x + (size_t)blockSample * 256;
        for (int i = tid; i < nval; i += NT) {
            int s = i >> 8, p = i & 255;
            int ih = p >> 4, iw = p & 15;
            sXin[s * 400 + (ih + 2) * 20 + (iw + 2)] = gx[i];
        }
    }
    __syncthreads();

    // ---------- Phase 2: conv1 5x5 s2, 1->12 ch, posbias, relu ----------
    // lane: quad q (2x2 output pixels), channel-group chg of 6 channels
    {
        const int q   = lane & 15;
        const int chg = lane >> 4;
        const int oh0 = (q >> 2) << 1;
        const int ow0 = (q & 3) << 1;
        const float* pbase = sXin + warp * 400 + (2 * oh0) * 20 + 2 * ow0;

        float p[7][8];
        #pragma unroll
        for (int i = 0; i < 7; i++) {
            float4 v0 = *(const float4*)(pbase + i * 20);
            float4 v1 = *(const float4*)(pbase + i * 20 + 4);
            p[i][0] = v0.x; p[i][1] = v0.y; p[i][2] = v0.z; p[i][3] = v0.w;
            p[i][4] = v1.x; p[i][5] = v1.y; p[i][6] = v1.z; p[i][7] = v1.w;
        }

        float* c1 = sC1 + warp * C1_SAMPLE;
        #pragma unroll
        for (int cc = 0; cc < 6; cc++) {
            const int c = chg * 6 + cc;
            const float4* w4 = (const float4*)(sW1 + c * 28);
            float w[28];
            #pragma unroll
            for (int i = 0; i < 7; i++) {
                float4 v = w4[i];
                w[4 * i] = v.x; w[4 * i + 1] = v.y;
                w[4 * i + 2] = v.z; w[4 * i + 3] = v.w;
            }
            float a00 = 0.f, a01 = 0.f, a10 = 0.f, a11 = 0.f;
            #pragma unroll
            for (int ki = 0; ki < 5; ki++)
                #pragma unroll
                for (int kj = 0; kj < 5; kj++) {
                    const float wv = w[ki * 5 + kj];
                    a00 = fmaf(p[ki][kj],         wv, a00);
                    a01 = fmaf(p[ki][kj + 2],     wv, a01);
                    a10 = fmaf(p[ki + 2][kj],     wv, a10);
                    a11 = fmaf(p[ki + 2][kj + 2], wv, a11);
                }
            const float* b = sB1 + c * 64;
            float2 b0 = *(const float2*)(b + oh0 * 8 + ow0);
            float2 b1 = *(const float2*)(b + (oh0 + 1) * 8 + ow0);
            // store to COMPACT interior: row stride 12, cols 0..7
            float* o = c1 + C1COFF(c);
            *(float2*)(o + oh0 * 12 + ow0) =
                make_float2(fmaxf(a00 + b0.x, 0.f), fmaxf(a01 + b0.y, 0.f));
            *(float2*)(o + (oh0 + 1) * 12 + ow0) =
                make_float2(fmaxf(a10 + b1.x, 0.f), fmaxf(a11 + b1.y, 0.f));
        }
    }
    __syncwarp();

    // ---------- Phase 3: grouped conv2 on interior-only c1 ----------
    // lane<24: oc = lane>>1, half = lane&1 (output rows {0,1} / {2,3}).
    // Padded row pr = 4*half + j (j=0..6); interior R = pr-2, predicated.
    // ki = j - 2*r'  (independent of half -> uniform, compile-time).
    // Out-of-interior col taps culled at compile time (folded into bias).
    if (lane < 24) {
        const int oc   = lane >> 1;
        const int half = lane & 1;
        const int g    = oc >> 2;
        const float* c1    = sC1 + warp * C1_SAMPLE;
        const float* wbase = sW2 + oc * W2_OC_STRIDE;

        float acc[2][4];
        #pragma unroll
        for (int r = 0; r < 2; r++)
            #pragma unroll
            for (int c = 0; c < 4; c++) acc[r][c] = 0.f;

        #pragma unroll
        for (int ic = 0; ic < 8; ic++) {
            const int inch = ic + ((g == 1) ? 4 : ((g == 2 && ic >= 4) ? 4 : 0));
            const float* ib = c1 + C1COFF(inch);

            const float4* w4 = (const float4*)(wbase + ic * 28);
            float w[28];
            #pragma unroll
            for (int i = 0; i < 7; i++) {
                float4 v = w4[i];
                w[4 * i] = v.x; w[4 * i + 1] = v.y;
                w[4 * i + 2] = v.z; w[4 * i + 3] = v.w;
            }

            #pragma unroll
            for (int j = 0; j < 7; j++) {
                const int R = 4 * half + j - 2;        // interior row
                float4 f0, f1;
                if ((unsigned)R < 8u) {
                    f0 = *(const float4*)(ib + R * 12);
                    f1 = *(const float4*)(ib + R * 12 + 4);
                } else {
                    f0 = make_float4(0.f, 0.f, 0.f, 0.f);
                    f1 = f0;
                }
                float row8[8] = {f0.x, f0.y, f0.z, f0.w,
                                 f1.x, f1.y, f1.z, f1.w};
                #pragma unroll
                for (int rp = 0; rp < 2; rp++) {
                    const int ki = j - 2 * rp;
                    if (ki < 0 || ki > 4) continue;    // compile-time
                    #pragma unroll
                    for (int c = 0; c < 4; c++)
                        #pragma unroll
                        for (int kj = 0; kj < 5; kj++) {
                            const int pc = 2 * c + kj; // padded col
                            if (pc < 2 || pc > 9) continue;  // compile-time cull
                            acc[rp][c] = fmaf(row8[pc - 2],
                                              w[ki * 5 + kj], acc[rp][c]);
                        }
                }
            }
        }

        // epilogue: adjusted bias + relu, 2 float4 stores
        float* c2 = sC2 + warp * C2_STRIDE;
        const int rowb = oc * 16 + half * 8;
        float4 bA = *(const float4*)(sB2 + rowb);
        float4 bB = *(const float4*)(sB2 + rowb + 4);
        float4 oA, oB;
        oA.x = fmaxf(acc[0][0] + bA.x, 0.f); oA.y = fmaxf(acc[0][1] + bA.y, 0.f);
        oA.z = fmaxf(acc[0][2] + bA.z, 0.f); oA.w = fmaxf(acc[0][3] + bA.w, 0.f);
        oB.x = fmaxf(acc[1][0] + bB.x, 0.f); oB.y = fmaxf(acc[1][1] + bB.y, 0.f);
        oB.z = fmaxf(acc[1][2] + bB.z, 0.f); oB.w = fmaxf(acc[1][3] + bB.w, 0.f);
        *(float4*)(c2 + rowb)     = oA;
        *(float4*)(c2 + rowb + 4) = oB;
    }
    __syncwarp();

    // ---------- Phase 4: fc1 192->30 (padded to 32), relu ----------
    // lane = (neuron-quad L = lane&7, k-slice ks = lane>>3)
    {
        const int L  = lane & 7;
        const int ks = lane >> 3;
        const float4* a4 = (const float4*)(sC2 + warp * C2_STRIDE + ks * 48);
        float4 acc = make_float4(0.f, 0.f, 0.f, 0.f);
        #pragma unroll
        for (int i = 0; i < 12; i++) {
            float4 av = a4[i];
            const float4* wr = (const float4*)(gW3p + (ks * 48 + 4 * i) * 32 + 4 * L);
            float4 w0 = __ldg(wr);
            float4 w1 = __ldg(wr + 8);
            float4 w2 = __ldg(wr + 16);
            float4 w3 = __ldg(wr + 24);
            acc.x = fmaf(av.x, w0.x, acc.x); acc.y = fmaf(av.x, w0.y, acc.y);
            acc.z = fmaf(av.x, w0.z, acc.z); acc.w = fmaf(av.x, w0.w, acc.w);
            acc.x = fmaf(av.y, w1.x, acc.x); acc.y = fmaf(av.y, w1.y, acc.y);
            acc.z = fmaf(av.y, w1.z, acc.z); acc.w = fmaf(av.y, w1.w, acc.w);
            acc.x = fmaf(av.z, w2.x, acc.x); acc.y = fmaf(av.z, w2.y, acc.y);
            acc.z = fmaf(av.z, w2.z, acc.z); acc.w = fmaf(av.z, w2.w, acc.w);
            acc.x = fmaf(av.w, w3.x, acc.x); acc.y = fmaf(av.w, w3.y, acc.y);
            acc.z = fmaf(av.w, w3.z, acc.z); acc.w = fmaf(av.w, w3.w, acc.w);
        }
        #pragma unroll
        for (int off = 16; off >= 8; off >>= 1) {
            acc.x += __shfl_xor_sync(0xffffffffu, acc.x, off);
            acc.y += __shfl_xor_sync(0xffffffffu, acc.y, off);
            acc.z += __shfl_xor_sync(0xffffffffu, acc.z, off);
            acc.w += __shfl_xor_sync(0xffffffffu, acc.w, off);
        }
        if (ks == 0) {
            float4 b = *(const float4*)(sB3 + 4 * L);
            float4 o;
            o.x = fmaxf(acc.x + b.x, 0.f); o.y = fmaxf(acc.y + b.y, 0.f);
            o.z = fmaxf(acc.z + b.z, 0.f); o.w = fmaxf(acc.w + b.w, 0.f);
            *(float4*)(sF1 + warp * 32 + 4 * L) = o;
        }
    }
    __syncwarp();

    // ---------- Phase 5: fc2 30->10, direct global store ----------
    if (lane < 10) {
        const float* f = sF1 + warp * 32;
        float acc = sBo[lane];
        #pragma unroll
        for (int k = 0; k < 30; k++)
            acc = fmaf(f[k], sWo[k * 10 + lane], acc);
        const int s = blockSample + warp;
        if (s < B) out[(size_t)s * 10 + lane] = acc;
    }
}

extern "C" void kernel_launch(void* const* d_in, const int* in_sizes, int n_in,
                              void* d_out, int out_size) {
    const float* x    = (const float*)d_in[0];
    const float* H1w  = (const float*)d_in[1];
    const float* H1b  = (const float*)d_in[2];
    const float* H2w  = (const float*)d_in[3];
    const float* H2b  = (const float*)d_in[4];
    const float* H3w  = (const float*)d_in[5];
    const float* H3b  = (const float*)d_in[6];
    const float* outw = (const float*)d_in[7];
    const float* outb = (const float*)d_in[8];

    const int B = in_sizes[0] / 256;
    const int blocks = (B + SPB - 1) / SPB;
    const size_t smem = SMEM_FLOATS * sizeof(float);

    prep_kernel<<<24, 256>>>(H1w, H2w, H3w, H2b);

    cudaFuncSetAttribute(modernnet_kernel,
                         cudaFuncAttributeMaxDynamicSharedMemorySize, (int)smem);

    modernnet_kernel<<<blocks, NT, smem>>>(x, H1b, H3b, outw, outb,
                                           (float*)d_out, B);
}